// round 2
// baseline (speedup 1.0000x reference)
#include <cuda_runtime.h>
#include <cstddef>

// Problem constants
#define BB 256
#define TT 300
#define CC 1152
#define OO 285
#define OPAD 320          // O padded to 5*64 for clean GEMM tiling
#define TSPLIT 4
#define TCHUNK 75         // 300 / 4
#define CSPLIT 9
#define CPS 128           // C per split: 9*128 = 1152
#define CCH 32            // c-chunk per smem stage
#define C4 (CC/4)         // 288 float4 per row

// Scratch (device globals — no allocation allowed)
__device__ float g_zpart[TSPLIT][BB][CC];     // raw T-partial sums of x
__device__ float g_zT[CC][BB];                // z_eff transposed: [c][b]
__device__ float g_WT[CC][OPAD];              // W transposed: [c][o], zero-padded
__device__ float g_pout[CSPLIT][BB][OPAD];    // GEMM C-split partials

// ---------------------------------------------------------------------------
// Kernel 1: reduce x over T (split 4 ways). One block = (batch b, T-chunk ts).
// 288 threads, each owns one float4 column, streams 75 rows.
// ---------------------------------------------------------------------------
__global__ void reduce_kernel(const float4* __restrict__ x) {
    const int b  = blockIdx.x;
    const int ts = blockIdx.y;
    const int tid = threadIdx.x;          // 0..287

    const float4* p = x + ((size_t)b * TT + (size_t)ts * TCHUNK) * C4 + tid;
    float sx = 0.f, sy = 0.f, sz = 0.f, sw = 0.f;

    #pragma unroll 5
    for (int t = 0; t < TCHUNK; ++t) {
        float4 v = p[(size_t)t * C4];
        sx += v.x; sy += v.y; sz += v.z; sw += v.w;
    }
    float4 s; s.x = sx; s.y = sy; s.z = sz; s.w = sw;
    ((float4*)g_zpart[ts][b])[tid] = s;
}

// ---------------------------------------------------------------------------
// Kernel 2: combine the 4 T-partials, apply affine (sum/64 - 2*T), transpose
// to zT[c][b]. 32x32 tile transpose, blockDim (32,8).
// ---------------------------------------------------------------------------
__global__ void combine_z_kernel() {
    __shared__ float tile[32][33];
    const int c0 = blockIdx.x * 32;
    const int b0 = blockIdx.y * 32;
    const int tx = threadIdx.x, ty = threadIdx.y;

    #pragma unroll
    for (int k = 0; k < 4; ++k) {
        int bl = ty + k * 8;
        int b = b0 + bl;
        int c = c0 + tx;
        float s = 0.f;
        #pragma unroll
        for (int ts = 0; ts < TSPLIT; ++ts) s += g_zpart[ts][b][c];
        tile[bl][tx] = s * (1.0f / 64.0f) - 2.0f * (float)TT;
    }
    __syncthreads();
    #pragma unroll
    for (int k = 0; k < 4; ++k) {
        int cl = ty + k * 8;
        g_zT[c0 + cl][b0 + tx] = tile[tx][cl];
    }
}

// ---------------------------------------------------------------------------
// Kernel 3: transpose W[285][1152] -> WT[c][o] (o padded to 320 with zeros).
// blockDim (32,8), grid (36, 10).
// ---------------------------------------------------------------------------
__global__ void transpose_w_kernel(const float* __restrict__ W) {
    __shared__ float tile[32][33];
    const int c0 = blockIdx.x * 32;
    const int o0 = blockIdx.y * 32;
    const int tx = threadIdx.x, ty = threadIdx.y;

    #pragma unroll
    for (int k = 0; k < 4; ++k) {
        int ol = ty + k * 8;
        int o = o0 + ol;
        int c = c0 + tx;
        tile[ol][tx] = (o < OO) ? W[(size_t)o * CC + c] : 0.0f;
    }
    __syncthreads();
    #pragma unroll
    for (int k = 0; k < 4; ++k) {
        int cl = ty + k * 8;
        g_WT[c0 + cl][o0 + tx] = tile[tx][cl];
    }
}

// ---------------------------------------------------------------------------
// Kernel 4: C-split GEMM. Block tile 64o x 64b x 128c, grid (5, 4, 9) = 180.
// Per thread: 4x4 register tile; per k-step: 2x LDS.128 + 16 FFMA.
// Writes fp32 partials to g_pout[cs].
// ---------------------------------------------------------------------------
__global__ void gemm_kernel() {
    __shared__ float zs[CCH][64];
    __shared__ float ws[CCH][64];

    const int o0 = blockIdx.x * 64;
    const int b0 = blockIdx.y * 64;
    const int cs = blockIdx.z;
    const int tid = threadIdx.x;          // 0..255
    const int tx = tid & 15;              // o direction (4 outputs)
    const int ty = tid >> 4;              // b direction (4 outputs)
    // fill mapping: row = tid>>4 (+16), float4 column = tid&15
    const int lcc = tid >> 4;
    const int lf4 = tid & 15;

    float acc[4][4] = {};

    for (int ch = 0; ch < CPS / CCH; ++ch) {
        const int cbase = cs * CPS + ch * CCH;
        #pragma unroll
        for (int r = 0; r < 2; ++r) {
            int cc = lcc + r * 16;
            float4 zv = *(const float4*)&g_zT[cbase + cc][b0 + lf4 * 4];
            *(float4*)&zs[cc][lf4 * 4] = zv;
            float4 wv = *(const float4*)&g_WT[cbase + cc][o0 + lf4 * 4];
            *(float4*)&ws[cc][lf4 * 4] = wv;
        }
        __syncthreads();

        #pragma unroll
        for (int cc = 0; cc < CCH; ++cc) {
            float4 zv = *(const float4*)&zs[cc][ty * 4];
            float4 wv = *(const float4*)&ws[cc][tx * 4];
            acc[0][0] += zv.x * wv.x; acc[0][1] += zv.x * wv.y;
            acc[0][2] += zv.x * wv.z; acc[0][3] += zv.x * wv.w;
            acc[1][0] += zv.y * wv.x; acc[1][1] += zv.y * wv.y;
            acc[1][2] += zv.y * wv.z; acc[1][3] += zv.y * wv.w;
            acc[2][0] += zv.z * wv.x; acc[2][1] += zv.z * wv.y;
            acc[2][2] += zv.z * wv.z; acc[2][3] += zv.z * wv.w;
            acc[3][0] += zv.w * wv.x; acc[3][1] += zv.w * wv.y;
            acc[3][2] += zv.w * wv.z; acc[3][3] += zv.w * wv.w;
        }
        __syncthreads();
    }

    #pragma unroll
    for (int i = 0; i < 4; ++i) {
        float4 v;
        v.x = acc[i][0]; v.y = acc[i][1]; v.z = acc[i][2]; v.w = acc[i][3];
        *(float4*)&g_pout[cs][b0 + ty * 4 + i][o0 + tx * 4] = v;
    }
}

// ---------------------------------------------------------------------------
// Kernel 5: finalize — sum 9 partials, add bias*T, divide by length.
// ---------------------------------------------------------------------------
__global__ void finalize_kernel(const int* __restrict__ length,
                                const float* __restrict__ bias,
                                float* __restrict__ out) {
    const int b = blockIdx.x;
    const int o = threadIdx.x;            // 0..287
    if (o < OO) {
        float s = 0.f;
        #pragma unroll
        for (int cs = 0; cs < CSPLIT; ++cs) s += g_pout[cs][b][o];
        s += (float)TT * bias[o];
        out[(size_t)b * OO + o] = s / (float)length[b];
    }
}

// ---------------------------------------------------------------------------
extern "C" void kernel_launch(void* const* d_in, const int* in_sizes, int n_in,
                              void* d_out, int out_size) {
    (void)in_sizes; (void)n_in; (void)out_size;
    const float4* x   = (const float4*)d_in[0];
    const int*    len = (const int*)d_in[1];
    const float*  W   = (const float*)d_in[2];
    const float*  bia = (const float*)d_in[3];
    float* out = (float*)d_out;

    reduce_kernel<<<dim3(BB, TSPLIT), C4>>>(x);
    combine_z_kernel<<<dim3(CC / 32, BB / 32), dim3(32, 8)>>>();
    transpose_w_kernel<<<dim3(CC / 32, OPAD / 32), dim3(32, 8)>>>(W);
    gemm_kernel<<<dim3(OPAD / 64, BB / 64, CSPLIT), 256>>>();
    finalize_kernel<<<BB, C4>>>(len, bia, out);
}

// round 3
// speedup vs baseline: 1.0656x; 1.0656x over previous
#include <cuda_runtime.h>
#include <cstddef>

// Problem constants
#define BB 256
#define TT 300
#define CC 1152
#define OO 285
#define OPAD 320          // O padded to 5*64 for clean GEMM tiling
#define TSPLIT 4
#define TCHUNK 75         // 300 / 4
#define CSPLIT 7          // grid = 5*4*7 = 140 blocks -> exactly one wave on 148 SMs
#define CPS 160           // C per split (last split gets 192): 6*160 + 192 = 1152
#define CCH 32            // c-chunk per smem stage
#define C4 (CC/4)         // 288 float4 per row

// Scratch (device globals — no allocation allowed)
__device__ float g_zpart[TSPLIT][BB][CC];     // raw T-partial sums of x
__device__ float g_zT[CC][BB];                // z_eff transposed: [c][b]
__device__ float g_WT[CC][OPAD];              // W transposed: [c][o], zero-padded
__device__ float g_pout[CSPLIT][BB][OPAD];    // GEMM C-split partials

// ---------------------------------------------------------------------------
// Kernel 1: reduce x over T (split 4 ways). One block = (batch b, T-chunk ts).
// 288 threads, each owns one float4 column, streams 75 rows. ~DRAM roofline.
// ---------------------------------------------------------------------------
__global__ void reduce_kernel(const float4* __restrict__ x) {
    const int b  = blockIdx.x;
    const int ts = blockIdx.y;
    const int tid = threadIdx.x;          // 0..287

    const float4* p = x + ((size_t)b * TT + (size_t)ts * TCHUNK) * C4 + tid;
    float sx = 0.f, sy = 0.f, sz = 0.f, sw = 0.f;

    #pragma unroll 5
    for (int t = 0; t < TCHUNK; ++t) {
        float4 v = p[(size_t)t * C4];
        sx += v.x; sy += v.y; sz += v.z; sw += v.w;
    }
    float4 s; s.x = sx; s.y = sy; s.z = sz; s.w = sw;
    ((float4*)g_zpart[ts][b])[tid] = s;
}

// ---------------------------------------------------------------------------
// Kernel 2 (fused): blockIdx.y < 8  -> combine 4 T-partials + affine, transpose
//                                      into zT[c][b]      (36 x 8  tiles)
//                   blockIdx.y >= 8 -> transpose W into WT[c][o], zero-padded
//                                      (36 x 10 tiles)
// blockDim (32,8); 32x32 tiles via smem.
// ---------------------------------------------------------------------------
__global__ void prep_kernel(const float* __restrict__ W) {
    __shared__ float tile[32][33];
    const int c0 = blockIdx.x * 32;
    const int tx = threadIdx.x, ty = threadIdx.y;

    if (blockIdx.y < 8) {
        const int b0 = blockIdx.y * 32;
        #pragma unroll
        for (int k = 0; k < 4; ++k) {
            int bl = ty + k * 8;
            int b = b0 + bl;
            int c = c0 + tx;
            float s = 0.f;
            #pragma unroll
            for (int ts = 0; ts < TSPLIT; ++ts) s += g_zpart[ts][b][c];
            tile[bl][tx] = s * (1.0f / 64.0f) - 2.0f * (float)TT;
        }
        __syncthreads();
        #pragma unroll
        for (int k = 0; k < 4; ++k) {
            int cl = ty + k * 8;
            g_zT[c0 + cl][b0 + tx] = tile[tx][cl];
        }
    } else {
        const int o0 = (blockIdx.y - 8) * 32;
        #pragma unroll
        for (int k = 0; k < 4; ++k) {
            int ol = ty + k * 8;
            int o = o0 + ol;
            int c = c0 + tx;
            tile[ol][tx] = (o < OO) ? W[(size_t)o * CC + c] : 0.0f;
        }
        __syncthreads();
        #pragma unroll
        for (int k = 0; k < 4; ++k) {
            int cl = ty + k * 8;
            g_WT[c0 + cl][o0 + tx] = tile[tx][cl];
        }
    }
}

// ---------------------------------------------------------------------------
// Kernel 3: C-split GEMM, double-buffered smem with register prefetch.
// Block tile 64o x 64b, grid (5, 4, 7) = 140 (one wave).
// Per thread: 4x4 register tile; per k-step: 2x LDS.128 + 16 FFMA.
// ---------------------------------------------------------------------------
__global__ void __launch_bounds__(256, 1) gemm_kernel() {
    __shared__ float zs[2][CCH][64];
    __shared__ float ws[2][CCH][64];

    const int o0 = blockIdx.x * 64;
    const int b0 = blockIdx.y * 64;
    const int cs = blockIdx.z;
    const int kbeg = cs * CPS;
    const int nch = ((cs == CSPLIT - 1) ? (CC - kbeg) : CPS) / CCH;  // 5 or 6

    const int tid = threadIdx.x;          // 0..255
    const int tx = tid & 15;              // o direction (4 outputs)
    const int ty = tid >> 4;              // b direction (4 outputs)
    const int lcc = tid >> 4;             // fill: smem row (and +16)
    const int lf4 = tid & 15;             // fill: float4 column

    float acc[4][4] = {};
    float4 pz[2], pw[2];

    // prologue: fetch chunk 0
    #pragma unroll
    for (int r = 0; r < 2; ++r) {
        int c = kbeg + lcc + r * 16;
        pz[r] = *(const float4*)&g_zT[c][b0 + lf4 * 4];
        pw[r] = *(const float4*)&g_WT[c][o0 + lf4 * 4];
    }
    #pragma unroll
    for (int r = 0; r < 2; ++r) {
        *(float4*)&zs[0][lcc + r * 16][lf4 * 4] = pz[r];
        *(float4*)&ws[0][lcc + r * 16][lf4 * 4] = pw[r];
    }
    __syncthreads();

    for (int ch = 0; ch < nch; ++ch) {
        const int cur = ch & 1;
        const int nxt = cur ^ 1;
        const bool more = (ch + 1 < nch);

        if (more) {
            const int cb = kbeg + (ch + 1) * CCH;
            #pragma unroll
            for (int r = 0; r < 2; ++r) {
                int c = cb + lcc + r * 16;
                pz[r] = *(const float4*)&g_zT[c][b0 + lf4 * 4];
                pw[r] = *(const float4*)&g_WT[c][o0 + lf4 * 4];
            }
        }

        #pragma unroll
        for (int cc = 0; cc < CCH; ++cc) {
            float4 zv = *(const float4*)&zs[cur][cc][ty * 4];
            float4 wv = *(const float4*)&ws[cur][cc][tx * 4];
            acc[0][0] += zv.x * wv.x; acc[0][1] += zv.x * wv.y;
            acc[0][2] += zv.x * wv.z; acc[0][3] += zv.x * wv.w;
            acc[1][0] += zv.y * wv.x; acc[1][1] += zv.y * wv.y;
            acc[1][2] += zv.y * wv.z; acc[1][3] += zv.y * wv.w;
            acc[2][0] += zv.z * wv.x; acc[2][1] += zv.z * wv.y;
            acc[2][2] += zv.z * wv.z; acc[2][3] += zv.z * wv.w;
            acc[3][0] += zv.w * wv.x; acc[3][1] += zv.w * wv.y;
            acc[3][2] += zv.w * wv.z; acc[3][3] += zv.w * wv.w;
        }

        if (more) {
            __syncthreads();
            #pragma unroll
            for (int r = 0; r < 2; ++r) {
                *(float4*)&zs[nxt][lcc + r * 16][lf4 * 4] = pz[r];
                *(float4*)&ws[nxt][lcc + r * 16][lf4 * 4] = pw[r];
            }
            __syncthreads();
        }
    }

    #pragma unroll
    for (int i = 0; i < 4; ++i) {
        float4 v;
        v.x = acc[i][0]; v.y = acc[i][1]; v.z = acc[i][2]; v.w = acc[i][3];
        *(float4*)&g_pout[cs][b0 + ty * 4 + i][o0 + tx * 4] = v;
    }
}

// ---------------------------------------------------------------------------
// Kernel 4: finalize — sum 7 partials, add bias*T, divide by length.
// ---------------------------------------------------------------------------
__global__ void finalize_kernel(const int* __restrict__ length,
                                const float* __restrict__ bias,
                                float* __restrict__ out) {
    const int b = blockIdx.x;
    const int o = threadIdx.x;            // 0..287
    if (o < OO) {
        float s = 0.f;
        #pragma unroll
        for (int cs = 0; cs < CSPLIT; ++cs) s += g_pout[cs][b][o];
        s += (float)TT * bias[o];
        out[(size_t)b * OO + o] = s / (float)length[b];
    }
}

// ---------------------------------------------------------------------------
extern "C" void kernel_launch(void* const* d_in, const int* in_sizes, int n_in,
                              void* d_out, int out_size) {
    (void)in_sizes; (void)n_in; (void)out_size;
    const float4* x   = (const float4*)d_in[0];
    const int*    len = (const int*)d_in[1];
    const float*  W   = (const float*)d_in[2];
    const float*  bia = (const float*)d_in[3];
    float* out = (float*)d_out;

    reduce_kernel<<<dim3(BB, TSPLIT), C4>>>(x);
    prep_kernel<<<dim3(CC / 32, 18), dim3(32, 8)>>>(W);
    gemm_kernel<<<dim3(OPAD / 64, BB / 64, CSPLIT), 256>>>();
    finalize_kernel<<<BB, C4>>>(len, bia, out);
}